// round 13
// baseline (speedup 1.0000x reference)
#include <cuda_runtime.h>
#include <cuda_bf16.h>
#include <cuda_fp16.h>
#include <math.h>
#include <stdint.h>

// Problem constants
#define B 4
#define N 2048
#define D 1024
#define H 16
#define HD 64
#define BN (B * N)            // 8192
#define SCALE 0.125f

// Scratch (device globals; u32 = packed fp16x2)
__device__ uint32_t g_xh[BN * 512];        // x fp16, d-pairs
__device__ uint32_t g_wqkvh[3072 * 512];   // Wqkv^T fp16 [n][kpair]
__device__ uint32_t g_wprojh[1024 * 512];  // Wproj^T fp16 [n][kpair]
__device__ uint32_t g_qkvh[BN * 1536];     // qkv fp16, col-pairs
__device__ uint32_t g_atth[BN * 512];      // att fp16, d-pairs
__device__ uint32_t g_vth[64 * 64 * 1024]; // V^T fp16 [bh][d][keypair]

// ---------------------------------------------------------------------------
// helpers
// ---------------------------------------------------------------------------
__device__ __forceinline__ uint32_t pack_h2(float x0, float x1) {
    __half2 hh = __floats2half2_rn(x0, x1);
    return *reinterpret_cast<uint32_t*>(&hh);
}
// fp16 mma, fp32 accumulate
__device__ __forceinline__ void mma16h(float* c, const uint32_t* a, const uint32_t* b) {
    asm volatile(
        "mma.sync.aligned.m16n8k16.row.col.f32.f16.f16.f32 "
        "{%0,%1,%2,%3}, {%4,%5,%6,%7}, {%8,%9}, {%0,%1,%2,%3};"
        : "+f"(c[0]), "+f"(c[1]), "+f"(c[2]), "+f"(c[3])
        : "r"(a[0]), "r"(a[1]), "r"(a[2]), "r"(a[3]), "r"(b[0]), "r"(b[1]));
}
// fp16 mma, fp16 accumulate (2 u32 regs hold 4 halves)
__device__ __forceinline__ void mma16hh(uint32_t* c, const uint32_t* a, const uint32_t* b) {
    asm volatile(
        "mma.sync.aligned.m16n8k16.row.col.f16.f16.f16.f16 "
        "{%0,%1}, {%2,%3,%4,%5}, {%6,%7}, {%0,%1};"
        : "+r"(c[0]), "+r"(c[1])
        : "r"(a[0]), "r"(a[1]), "r"(a[2]), "r"(a[3]), "r"(b[0]), "r"(b[1]));
}
__device__ __forceinline__ void ldsm4(uint32_t addr, uint32_t* r) {
    asm volatile("ldmatrix.sync.aligned.m8n8.x4.shared.b16 {%0,%1,%2,%3}, [%4];"
        : "=r"(r[0]), "=r"(r[1]), "=r"(r[2]), "=r"(r[3]) : "r"(addr));
}
__device__ __forceinline__ uint32_t smem_u32(const void* p) {
    uint32_t a;
    asm("{ .reg .u64 t; cvta.to.shared.u64 t, %1; cvt.u32.u64 %0, t; }" : "=r"(a) : "l"(p));
    return a;
}
#define CP_ASYNC16(dst, src) \
    asm volatile("cp.async.cg.shared.global [%0], [%1], 16;" :: "r"(dst), "l"(src))
#define CP_COMMIT() asm volatile("cp.async.commit_group;" ::: "memory")
#define CP_WAIT(n)  asm volatile("cp.async.wait_group %0;" :: "n"(n) : "memory")

// ---------------------------------------------------------------------------
// split_x: x fp32 -> fp16 pairs (d-pairs)
// ---------------------------------------------------------------------------
__global__ void split_x_k(const float* __restrict__ x, uint32_t* __restrict__ xh)
{
    int i = blockIdx.x * blockDim.x + threadIdx.x;
    float4 v = ((const float4*)x)[i];
    ((uint2*)xh)[i] = make_uint2(pack_h2(v.x, v.y), pack_h2(v.z, v.w));
}

// ---------------------------------------------------------------------------
// wsplit2: both weight matrices fp32 -> W^T fp16 [n][kpair] in ONE launch.
// ---------------------------------------------------------------------------
__global__ __launch_bounds__(256) void wsplit2_k(
    const float* __restrict__ Wqkv, const float* __restrict__ Wproj,
    uint32_t* __restrict__ Wqkvh, uint32_t* __restrict__ Wprojh)
{
    __shared__ float sw[64 * 68];
    const int tid = threadIdx.x;
    const int z = blockIdx.z;
    const float* W;
    uint32_t* Wth;
    int Nn, n0;
    if (z < 3) { W = Wqkv;  Wth = Wqkvh;  Nn = 3072; n0 = (z * 16 + blockIdx.x) * 64; }
    else       { W = Wproj; Wth = Wprojh; Nn = 1024; n0 = blockIdx.x * 64; }
    const int k0 = blockIdx.y * 64;
#pragma unroll
    for (int i = 0; i < 4; i++) {
        int f = tid + i * 256;
        int k = f >> 4, nq = f & 15;
        float4 v = *(const float4*)&W[(size_t)(k0 + k) * Nn + n0 + nq * 4];
        *(float4*)&sw[k * 68 + nq * 4] = v;
    }
    __syncthreads();
    const int n = tid >> 2, kq = tid & 3;
    uint32_t hb[8];
#pragma unroll
    for (int j = 0; j < 8; j++) {
        int kp = kq * 8 + j;
        hb[j] = pack_h2(sw[(2 * kp) * 68 + n], sw[(2 * kp + 1) * 68 + n]);
    }
    size_t o = (size_t)(n0 + n) * 512 + k0 / 2 + kq * 8;
    *(uint4*)&Wth[o]     = make_uint4(hb[0], hb[1], hb[2], hb[3]);
    *(uint4*)&Wth[o + 4] = make_uint4(hb[4], hb[5], hb[6], hb[7]);
}

// ---------------------------------------------------------------------------
// vtrans: qkv (v section, d-pairs fp16) -> V^T fp16 [bh][d][keypair]
// ---------------------------------------------------------------------------
__global__ __launch_bounds__(256) void vtrans_k(
    const uint32_t* __restrict__ qh, uint32_t* __restrict__ vth)
{
    __shared__ uint32_t sc[32 * 66];
    const int tid = threadIdx.x;
    const int kb = blockIdx.x, bh = blockIdx.y;
    const int b = bh >> 4, h = bh & 15;
#pragma unroll
    for (int i = 0; i < 2; i++) {
        int f = tid + i * 256;
        int key = f >> 3, q = (f & 7) * 4;
        size_t src = (size_t)(b * 2048 + kb * 64 + key) * 1536 + 1024 + h * 32 + q;
        uint4 vh = *(const uint4*)&qh[src];
        sc[(q + 0) * 66 + key] = vh.x; sc[(q + 1) * 66 + key] = vh.y;
        sc[(q + 2) * 66 + key] = vh.z; sc[(q + 3) * 66 + key] = vh.w;
    }
    __syncthreads();
#pragma unroll
    for (int i = 0; i < 8; i++) {
        int f = tid + i * 256;
        int d = f >> 5, kp = f & 31;
        uint32_t sel = (d & 1) ? 0x7632u : 0x5410u;
        uint2 wh = *(const uint2*)&sc[(d >> 1) * 66 + 2 * kp];
        size_t dst = (size_t)(bh * 64 + d) * 1024 + kb * 32 + kp;
        vth[dst] = __byte_perm(wh.x, wh.y, sel);
    }
}

// ---------------------------------------------------------------------------
// GEMM fp16 1-term: C = A @ W + bias.  BK=32, THREE-stage cp.async pipeline
// (prefetch depth 2, CP_WAIT(1)). 128x128 tile, 256 thr, warps 4(m)x2(n).
// buf (u32): A@0, B@2560 -> 5120/buf, 3 bufs = 61440 B.
// ---------------------------------------------------------------------------
#define TSTR 20
#define TILE_U32 2560
#define BUF1_U32 5120
#define G1SMEM_BYTES (3 * BUF1_U32 * 4)

template <bool SPLIT_OUT>
__global__ __launch_bounds__(256, 2) void gemm_1t(
    const uint32_t* __restrict__ Ah_g,
    const uint32_t* __restrict__ Bh_g,
    const float* __restrict__ bias,
    float* __restrict__ C, uint32_t* __restrict__ Ch,
    int M, int Nn, int K)
{
    extern __shared__ uint32_t sm[];
    const uint32_t sb = smem_u32(sm);
    const int tid = threadIdx.x;
    const int lane = tid & 31, warp = tid >> 5;
    const int g = lane >> 2, cq = lane & 3;
    const int wm = (warp >> 1) * 32, wn = (warp & 1) * 64;
    const int m0 = blockIdx.y * 128, n0 = blockIdx.x * 128;
    const int kwtot = K / 2;

    const int a_r = lane & 15, a_c = (lane >> 4) * 4;

    float acc[2][8][4];
#pragma unroll
    for (int mt = 0; mt < 2; mt++)
#pragma unroll
        for (int nt = 0; nt < 8; nt++)
#pragma unroll
            for (int k = 0; k < 4; k++) acc[mt][nt][k] = 0.0f;

    auto issue = [&](int c, int buf) {
        const int kw = c * 16;
        const uint32_t bb = sb + buf * (BUF1_U32 * 4);
#pragma unroll
        for (int i = 0; i < 2; i++) {
            int f = tid + i * 256;
            int r = f >> 2, q = (f & 3) * 4;
            uint32_t d0 = bb + (r * TSTR + q) * 4;
            CP_ASYNC16(d0,                &Ah_g[(size_t)(m0 + r) * kwtot + kw + q]);
            CP_ASYNC16(d0 + TILE_U32 * 4, &Bh_g[(size_t)(n0 + r) * kwtot + kw + q]);
        }
        CP_COMMIT();
    };

    const int nch = K / 32;
    issue(0, 0);
    issue(1, 1);
    int buf = 0;
    for (int c = 0; c < nch; c++) {
        if (c + 1 < nch) { CP_WAIT(1); } else { CP_WAIT(0); }
        __syncthreads();
        if (c + 2 < nch) {
            int nb = buf + 2; if (nb >= 3) nb -= 3;
            issue(c + 2, nb);
        }

        const uint32_t bufb = sb + buf * (BUF1_U32 * 4);
#pragma unroll
        for (int kc = 0; kc < 2; kc++) {
            uint32_t ah[2][4];
#pragma unroll
            for (int mt = 0; mt < 2; mt++)
                ldsm4(bufb + ((wm + mt * 16 + a_r) * TSTR + kc * 8 + a_c) * 4, ah[mt]);
#pragma unroll
            for (int ntp = 0; ntp < 4; ntp++) {
                uint32_t b4[4];
                ldsm4(bufb + TILE_U32 * 4 +
                      ((wn + ntp * 16 + a_r) * TSTR + kc * 8 + a_c) * 4, b4);
                uint32_t b0[2] = {b4[0], b4[2]};
                uint32_t b1[2] = {b4[1], b4[3]};
#pragma unroll
                for (int mt = 0; mt < 2; mt++) mma16h(acc[mt][2 * ntp], ah[mt], b0);
#pragma unroll
                for (int mt = 0; mt < 2; mt++) mma16h(acc[mt][2 * ntp + 1], ah[mt], b1);
            }
        }
        if (++buf == 3) buf = 0;
    }

#pragma unroll
    for (int mt = 0; mt < 2; mt++) {
#pragma unroll
        for (int nt = 0; nt < 8; nt++) {
            int row = m0 + wm + mt * 16 + g;
            int col = n0 + wn + nt * 8 + 2 * cq;
            float b0 = bias[col], b1 = bias[col + 1];
            float v00 = acc[mt][nt][0] + b0, v01 = acc[mt][nt][1] + b1;
            float v10 = acc[mt][nt][2] + b0, v11 = acc[mt][nt][3] + b1;
            if (SPLIT_OUT) {
                int wc = col >> 1;
                Ch[(size_t)row * (Nn / 2) + wc]       = pack_h2(v00, v01);
                Ch[(size_t)(row + 8) * (Nn / 2) + wc] = pack_h2(v10, v11);
            } else {
                *(float2*)&C[(size_t)row * Nn + col] = make_float2(v00, v01);
                *(float2*)&C[(size_t)(row + 8) * Nn + col] = make_float2(v10, v11);
            }
        }
    }
}

// ---------------------------------------------------------------------------
// Attention: QK in fp16-ACCUM mma (half pipe cost; S-path error suppressed),
// PV in fp32-accum. 64-key tiles, THREE-stage KV pipeline, register P.
// smem u32: Q@0 (4608), 3 KV bufs of 4608 at 4608: KH@0, VH@2304.
// Total 18432 u32 = 73728 B.
// ---------------------------------------------------------------------------
#define QS2 36
#define KVBUF 4608
#define AKV0 4608
#define ATT_SMEM_U32 (4608 + 3 * KVBUF)

__global__ __launch_bounds__(256, 2) void attn_1t(
    const uint32_t* __restrict__ qh_g,
    const uint32_t* __restrict__ vth,
    uint32_t* __restrict__ atth)
{
    extern __shared__ uint32_t sm[];
    const uint32_t sb = smem_u32(sm);

    const int tid  = threadIdx.x;
    const int lane = tid & 31, warp = tid >> 5;
    const int g = lane >> 2, cq = lane & 3;
    const int b = blockIdx.z, h = blockIdx.y;
    const int bh = b * H + h;
    const int q0 = blockIdx.x * 128;

    const int a_r = lane & 15, a_c = (lane >> 4) * 4;

    // stage Q (group 0)
#pragma unroll
    for (int i = 0; i < 4; i++) {
        int f = tid + i * 256;
        int row = f >> 3, q = (f & 7) * 4;
        size_t src = (size_t)(b * 2048 + q0 + row) * 1536 + h * 32 + q;
        CP_ASYNC16(sb + (row * QS2 + q) * 4, &qh_g[src]);
    }
    CP_COMMIT();

    auto issue_kv = [&](int kb, int buf) {
        const uint32_t kvb = AKV0 + buf * KVBUF;
#pragma unroll
        for (int i = 0; i < 2; i++) {
            int f = tid + i * 256;
            int row = f >> 3, q = (f & 7) * 4;
            size_t ksrc = (size_t)(b * 2048 + kb * 64 + row) * 1536 + 512 + h * 32 + q;
            CP_ASYNC16(sb + (kvb + row * QS2 + q) * 4, &qh_g[ksrc]);
            size_t vsrc = (size_t)(bh * 64 + row) * 1024 + kb * 32 + q;
            CP_ASYNC16(sb + (kvb + 2304 + row * QS2 + q) * 4, &vth[vsrc]);
        }
        CP_COMMIT();
    };
    issue_kv(0, 0);
    issue_kv(1, 1);

    float m0v = -1e30f, m1v = -1e30f, l0s = 0.0f, l1s = 0.0f;
    float o[8][4];
#pragma unroll
    for (int nt = 0; nt < 8; nt++)
#pragma unroll
        for (int k = 0; k < 4; k++) o[nt][k] = 0.0f;

    const int rb_ = warp * 16;
    const int NKB = N / 64;

    int buf = 0;
    for (int kb = 0; kb < NKB; kb++) {
        if (kb + 1 < NKB) { CP_WAIT(1); } else { CP_WAIT(0); }
        __syncthreads();
        if (kb + 2 < NKB) {
            int nb = buf + 2; if (nb >= 3) nb -= 3;
            issue_kv(kb + 2, nb);
        }

        const uint32_t kvb = AKV0 + buf * KVBUF;

        // S = Q @ K^T  (fp16 accumulate)
        uint32_t sh[8][2];
#pragma unroll
        for (int nt = 0; nt < 8; nt++) { sh[nt][0] = 0u; sh[nt][1] = 0u; }

#pragma unroll
        for (int kc = 0; kc < 4; kc++) {
            uint32_t qh4[4];
            ldsm4(sb + ((rb_ + a_r) * QS2 + kc * 8 + a_c) * 4, qh4);
#pragma unroll
            for (int ntp = 0; ntp < 4; ntp++) {
                uint32_t k4[4];
                ldsm4(sb + (kvb + (ntp * 16 + a_r) * QS2 + kc * 8 + a_c) * 4, k4);
                uint32_t k0[2] = {k4[0], k4[2]};
                uint32_t k1[2] = {k4[1], k4[3]};
                mma16hh(sh[2 * ntp], qh4, k0);
                mma16hh(sh[2 * ntp + 1], qh4, k1);
            }
        }

        // unpack to fp32 logits
        float s[8][4];
#pragma unroll
        for (int nt = 0; nt < 8; nt++) {
            float2 lo = __half22float2(*reinterpret_cast<__half2*>(&sh[nt][0]));
            float2 hi = __half22float2(*reinterpret_cast<__half2*>(&sh[nt][1]));
            s[nt][0] = lo.x; s[nt][1] = lo.y; s[nt][2] = hi.x; s[nt][3] = hi.y;
        }

        // online softmax -> register P fragments (fp16)
        float rm0 = -1e30f, rm1 = -1e30f;
#pragma unroll
        for (int nt = 0; nt < 8; nt++) {
            s[nt][0] *= SCALE; s[nt][1] *= SCALE; s[nt][2] *= SCALE; s[nt][3] *= SCALE;
            rm0 = fmaxf(rm0, fmaxf(s[nt][0], s[nt][1]));
            rm1 = fmaxf(rm1, fmaxf(s[nt][2], s[nt][3]));
        }
        rm0 = fmaxf(rm0, __shfl_xor_sync(0xffffffff, rm0, 1));
        rm0 = fmaxf(rm0, __shfl_xor_sync(0xffffffff, rm0, 2));
        rm1 = fmaxf(rm1, __shfl_xor_sync(0xffffffff, rm1, 1));
        rm1 = fmaxf(rm1, __shfl_xor_sync(0xffffffff, rm1, 2));

        float nm0 = fmaxf(m0v, rm0), nm1 = fmaxf(m1v, rm1);
        float a0 = __expf(m0v - nm0), a1 = __expf(m1v - nm1);
        m0v = nm0; m1v = nm1;

        uint32_t phg[8], phh[8];
        float rs0 = 0.0f, rs1 = 0.0f;
#pragma unroll
        for (int nt = 0; nt < 8; nt++) {
            float p0 = __expf(s[nt][0] - nm0);
            float p1 = __expf(s[nt][1] - nm0);
            float p2 = __expf(s[nt][2] - nm1);
            float p3 = __expf(s[nt][3] - nm1);
            rs0 += p0 + p1;
            rs1 += p2 + p3;
            phg[nt] = pack_h2(p0, p1);
            phh[nt] = pack_h2(p2, p3);
        }
        rs0 += __shfl_xor_sync(0xffffffff, rs0, 1);
        rs0 += __shfl_xor_sync(0xffffffff, rs0, 2);
        rs1 += __shfl_xor_sync(0xffffffff, rs1, 1);
        rs1 += __shfl_xor_sync(0xffffffff, rs1, 2);
        l0s = l0s * a0 + rs0;
        l1s = l1s * a1 + rs1;
#pragma unroll
        for (int nt = 0; nt < 8; nt++) {
            o[nt][0] *= a0; o[nt][1] *= a0; o[nt][2] *= a1; o[nt][3] *= a1;
        }

        // O += P @ V  (fp32 accumulate)
#pragma unroll
        for (int kcb = 0; kcb < 4; kcb++) {
            uint32_t ah4[4] = {phg[2 * kcb], phh[2 * kcb],
                               phg[2 * kcb + 1], phh[2 * kcb + 1]};
#pragma unroll
            for (int ntp = 0; ntp < 4; ntp++) {
                uint32_t v4[4];
                ldsm4(sb + (kvb + 2304 + (ntp * 16 + a_r) * QS2 + kcb * 8 + a_c) * 4, v4);
                uint32_t v0[2] = {v4[0], v4[2]};
                uint32_t v1[2] = {v4[1], v4[3]};
                mma16h(o[2 * ntp], ah4, v0);
                mma16h(o[2 * ntp + 1], ah4, v1);
            }
        }
        if (++buf == 3) buf = 0;
    }

    // normalize + write att (fp16 d-pairs)
    float inv0 = 1.0f / l0s, inv1 = 1.0f / l1s;
#pragma unroll
    for (int nt = 0; nt < 8; nt++) {
        int wc = h * 32 + nt * 4 + cq;
        size_t r0o = (size_t)(b * 2048 + q0 + rb_ + g) * 512 + wc;
        size_t r1o = (size_t)(b * 2048 + q0 + rb_ + g + 8) * 512 + wc;
        atth[r0o] = pack_h2(o[nt][0] * inv0, o[nt][1] * inv0);
        atth[r1o] = pack_h2(o[nt][2] * inv1, o[nt][3] * inv1);
    }
}

// ---------------------------------------------------------------------------
extern "C" void kernel_launch(void* const* d_in, const int* in_sizes, int n_in,
                              void* d_out, int out_size)
{
    const float* x     = (const float*)d_in[0];
    const float* Wqkv  = (const float*)d_in[1];
    const float* bqkv  = (const float*)d_in[2];
    const float* Wproj = (const float*)d_in[3];
    const float* bproj = (const float*)d_in[4];
    float* out = (float*)d_out;

    void* p;
    uint32_t *xh, *wqh, *wph, *qh, *ath, *vth;
    cudaGetSymbolAddress(&p, g_xh);     xh = (uint32_t*)p;
    cudaGetSymbolAddress(&p, g_wqkvh);  wqh = (uint32_t*)p;
    cudaGetSymbolAddress(&p, g_wprojh); wph = (uint32_t*)p;
    cudaGetSymbolAddress(&p, g_qkvh);   qh = (uint32_t*)p;
    cudaGetSymbolAddress(&p, g_atth);   ath = (uint32_t*)p;
    cudaGetSymbolAddress(&p, g_vth);    vth = (uint32_t*)p;

    cudaFuncSetAttribute(gemm_1t<true>,  cudaFuncAttributeMaxDynamicSharedMemorySize, G1SMEM_BYTES);
    cudaFuncSetAttribute(gemm_1t<false>, cudaFuncAttributeMaxDynamicSharedMemorySize, G1SMEM_BYTES);
    cudaFuncSetAttribute(attn_1t, cudaFuncAttributeMaxDynamicSharedMemorySize, ATT_SMEM_U32 * 4);

    // prep: convert x; transpose+convert both weights in one launch
    split_x_k<<<BN * D / 4 / 256, 256>>>(x, xh);
    wsplit2_k<<<dim3(16, 16, 4), 256>>>(Wqkv, Wproj, wqh, wph);

    // 1) qkv = x @ Wqkv + bqkv  (fp16 out)
    gemm_1t<true><<<dim3(3 * D / 128, BN / 128), 256, G1SMEM_BYTES>>>(
        xh, wqh, bqkv, nullptr, qh, BN, 3 * D, D);

    // 1b) build V^T (fp16)
    vtrans_k<<<dim3(N / 64, B * H), 256>>>(qh, vth);

    // 2) attention -> att (fp16 out)
    attn_1t<<<dim3(N / 128, H, B), 256, ATT_SMEM_U32 * 4>>>(qh, vth, ath);

    // 3) out = att @ Wproj + bproj  (fp32 out)
    gemm_1t<false><<<dim3(D / 128, BN / 128), 256, G1SMEM_BYTES>>>(
        ath, wph, bproj, out, nullptr, BN, D, D);
}

// round 14
// speedup vs baseline: 1.0406x; 1.0406x over previous
#include <cuda_runtime.h>
#include <cuda_bf16.h>
#include <cuda_fp16.h>
#include <math.h>
#include <stdint.h>

// Problem constants
#define B 4
#define N 2048
#define D 1024
#define H 16
#define HD 64
#define BN (B * N)            // 8192
#define SCALE 0.125f
#define LOG2E 1.44269504f

// Scratch (device globals; u32 = packed fp16x2)
__device__ uint32_t g_xh[BN * 512];        // x fp16, d-pairs
__device__ uint32_t g_wqkvh[3072 * 512];   // Wqkv^T fp16 [n][kpair]
__device__ uint32_t g_wprojh[1024 * 512];  // Wproj^T fp16 [n][kpair]
__device__ uint32_t g_qkvh[BN * 1536];     // qkv fp16, col-pairs
__device__ uint32_t g_atth[BN * 512];      // att fp16, d-pairs
__device__ uint32_t g_vth[64 * 64 * 1024]; // V^T fp16 [bh][d][keypair]

// ---------------------------------------------------------------------------
// helpers
// ---------------------------------------------------------------------------
__device__ __forceinline__ uint32_t pack_h2(float x0, float x1) {
    __half2 hh = __floats2half2_rn(x0, x1);
    return *reinterpret_cast<uint32_t*>(&hh);
}
__device__ __forceinline__ __half2 u2h(uint32_t x) {
    return *reinterpret_cast<__half2*>(&x);
}
// fp16 mma, fp32 accumulate
__device__ __forceinline__ void mma16h(float* c, const uint32_t* a, const uint32_t* b) {
    asm volatile(
        "mma.sync.aligned.m16n8k16.row.col.f32.f16.f16.f32 "
        "{%0,%1,%2,%3}, {%4,%5,%6,%7}, {%8,%9}, {%0,%1,%2,%3};"
        : "+f"(c[0]), "+f"(c[1]), "+f"(c[2]), "+f"(c[3])
        : "r"(a[0]), "r"(a[1]), "r"(a[2]), "r"(a[3]), "r"(b[0]), "r"(b[1]));
}
__device__ __forceinline__ void ldsm4(uint32_t addr, uint32_t* r) {
    asm volatile("ldmatrix.sync.aligned.m8n8.x4.shared.b16 {%0,%1,%2,%3}, [%4];"
        : "=r"(r[0]), "=r"(r[1]), "=r"(r[2]), "=r"(r[3]) : "r"(addr));
}
__device__ __forceinline__ uint32_t ex2h2(uint32_t t) {
    uint32_t r;
    asm("ex2.approx.f16x2 %0, %1;" : "=r"(r) : "r"(t));
    return r;
}
__device__ __forceinline__ uint32_t smem_u32(const void* p) {
    uint32_t a;
    asm("{ .reg .u64 t; cvta.to.shared.u64 t, %1; cvt.u32.u64 %0, t; }" : "=r"(a) : "l"(p));
    return a;
}
#define CP_ASYNC16(dst, src) \
    asm volatile("cp.async.cg.shared.global [%0], [%1], 16;" :: "r"(dst), "l"(src))
#define CP_COMMIT() asm volatile("cp.async.commit_group;" ::: "memory")
#define CP_WAIT(n)  asm volatile("cp.async.wait_group %0;" :: "n"(n) : "memory")

// ---------------------------------------------------------------------------
// prep: merged  x->fp16 (blocks [0, 8192))  +  weight transpose/convert
// (blocks [8192, 9216): 256 per z-slice, z<3 Wqkv, z==3 Wproj)
// ---------------------------------------------------------------------------
__global__ __launch_bounds__(256) void prep_k(
    const float* __restrict__ x, uint32_t* __restrict__ xh,
    const float* __restrict__ Wqkv, const float* __restrict__ Wproj,
    uint32_t* __restrict__ Wqkvh, uint32_t* __restrict__ Wprojh)
{
    __shared__ float sw[64 * 68];
    const int tid = threadIdx.x;
    const int bid = blockIdx.x;

    if (bid < 8192) {
        int i = bid * 256 + tid;
        float4 v = ((const float4*)x)[i];
        ((uint2*)xh)[i] = make_uint2(pack_h2(v.x, v.y), pack_h2(v.z, v.w));
        return;
    }
    const int b2 = bid - 8192;
    const int z = b2 >> 8, rem = b2 & 255;
    const float* W;
    uint32_t* Wth;
    int Nn, n0;
    if (z < 3) { W = Wqkv;  Wth = Wqkvh;  Nn = 3072; n0 = (z * 16 + (rem & 15)) * 64; }
    else       { W = Wproj; Wth = Wprojh; Nn = 1024; n0 = (rem & 15) * 64; }
    const int k0 = (rem >> 4) * 64;
#pragma unroll
    for (int i = 0; i < 4; i++) {
        int f = tid + i * 256;
        int k = f >> 4, nq = f & 15;
        float4 v = *(const float4*)&W[(size_t)(k0 + k) * Nn + n0 + nq * 4];
        *(float4*)&sw[k * 68 + nq * 4] = v;
    }
    __syncthreads();
    const int n = tid >> 2, kq = tid & 3;
    uint32_t hb[8];
#pragma unroll
    for (int j = 0; j < 8; j++) {
        int kp = kq * 8 + j;
        hb[j] = pack_h2(sw[(2 * kp) * 68 + n], sw[(2 * kp + 1) * 68 + n]);
    }
    size_t o = (size_t)(n0 + n) * 512 + k0 / 2 + kq * 8;
    *(uint4*)&Wth[o]     = make_uint4(hb[0], hb[1], hb[2], hb[3]);
    *(uint4*)&Wth[o + 4] = make_uint4(hb[4], hb[5], hb[6], hb[7]);
}

// ---------------------------------------------------------------------------
// vtrans: qkv (v section, d-pairs fp16) -> V^T fp16 [bh][d][keypair]
// ---------------------------------------------------------------------------
__global__ __launch_bounds__(256) void vtrans_k(
    const uint32_t* __restrict__ qh, uint32_t* __restrict__ vth)
{
    __shared__ uint32_t sc[32 * 66];
    const int tid = threadIdx.x;
    const int kb = blockIdx.x, bh = blockIdx.y;
    const int b = bh >> 4, h = bh & 15;
#pragma unroll
    for (int i = 0; i < 2; i++) {
        int f = tid + i * 256;
        int key = f >> 3, q = (f & 7) * 4;
        size_t src = (size_t)(b * 2048 + kb * 64 + key) * 1536 + 1024 + h * 32 + q;
        uint4 vh = *(const uint4*)&qh[src];
        sc[(q + 0) * 66 + key] = vh.x; sc[(q + 1) * 66 + key] = vh.y;
        sc[(q + 2) * 66 + key] = vh.z; sc[(q + 3) * 66 + key] = vh.w;
    }
    __syncthreads();
#pragma unroll
    for (int i = 0; i < 8; i++) {
        int f = tid + i * 256;
        int d = f >> 5, kp = f & 31;
        uint32_t sel = (d & 1) ? 0x7632u : 0x5410u;
        uint2 wh = *(const uint2*)&sc[(d >> 1) * 66 + 2 * kp];
        size_t dst = (size_t)(bh * 64 + d) * 1024 + kb * 32 + kp;
        vth[dst] = __byte_perm(wh.x, wh.y, sel);
    }
}

// ---------------------------------------------------------------------------
// GEMM fp16 1-term: C = A @ W + bias.  BK=32, double-buffered,
// single barrier per chunk. 128x128 tile, 256 thr, warps 4(m)x2(n).
// ---------------------------------------------------------------------------
#define TSTR 20
#define TILE_U32 2560
#define BUF1_U32 5120
#define G1SMEM_BYTES (2 * BUF1_U32 * 4)

template <bool SPLIT_OUT>
__global__ __launch_bounds__(256, 2) void gemm_1t(
    const uint32_t* __restrict__ Ah_g,
    const uint32_t* __restrict__ Bh_g,
    const float* __restrict__ bias,
    float* __restrict__ C, uint32_t* __restrict__ Ch,
    int M, int Nn, int K)
{
    extern __shared__ uint32_t sm[];
    const uint32_t sb = smem_u32(sm);
    const int tid = threadIdx.x;
    const int lane = tid & 31, warp = tid >> 5;
    const int g = lane >> 2, cq = lane & 3;
    const int wm = (warp >> 1) * 32, wn = (warp & 1) * 64;
    const int m0 = blockIdx.y * 128, n0 = blockIdx.x * 128;
    const int kwtot = K / 2;

    const int a_r = lane & 15, a_c = (lane >> 4) * 4;

    float acc[2][8][4];
#pragma unroll
    for (int mt = 0; mt < 2; mt++)
#pragma unroll
        for (int nt = 0; nt < 8; nt++)
#pragma unroll
            for (int k = 0; k < 4; k++) acc[mt][nt][k] = 0.0f;

    auto issue = [&](int c, int buf) {
        const int kw = c * 16;
        const uint32_t bb = sb + buf * (BUF1_U32 * 4);
#pragma unroll
        for (int i = 0; i < 2; i++) {
            int f = tid + i * 256;
            int r = f >> 2, q = (f & 3) * 4;
            uint32_t d0 = bb + (r * TSTR + q) * 4;
            CP_ASYNC16(d0,                &Ah_g[(size_t)(m0 + r) * kwtot + kw + q]);
            CP_ASYNC16(d0 + TILE_U32 * 4, &Bh_g[(size_t)(n0 + r) * kwtot + kw + q]);
        }
        CP_COMMIT();
    };

    const int nch = K / 32;
    issue(0, 0);
    for (int c = 0; c < nch; c++) {
        CP_WAIT(0);
        __syncthreads();
        if (c + 1 < nch) issue(c + 1, (c + 1) & 1);

        const uint32_t bufb = sb + (c & 1) * (BUF1_U32 * 4);
#pragma unroll
        for (int kc = 0; kc < 2; kc++) {
            uint32_t ah[2][4];
#pragma unroll
            for (int mt = 0; mt < 2; mt++)
                ldsm4(bufb + ((wm + mt * 16 + a_r) * TSTR + kc * 8 + a_c) * 4, ah[mt]);
#pragma unroll
            for (int ntp = 0; ntp < 4; ntp++) {
                uint32_t b4[4];
                ldsm4(bufb + TILE_U32 * 4 +
                      ((wn + ntp * 16 + a_r) * TSTR + kc * 8 + a_c) * 4, b4);
                uint32_t b0[2] = {b4[0], b4[2]};
                uint32_t b1[2] = {b4[1], b4[3]};
#pragma unroll
                for (int mt = 0; mt < 2; mt++) mma16h(acc[mt][2 * ntp], ah[mt], b0);
#pragma unroll
                for (int mt = 0; mt < 2; mt++) mma16h(acc[mt][2 * ntp + 1], ah[mt], b1);
            }
        }
    }

#pragma unroll
    for (int mt = 0; mt < 2; mt++) {
#pragma unroll
        for (int nt = 0; nt < 8; nt++) {
            int row = m0 + wm + mt * 16 + g;
            int col = n0 + wn + nt * 8 + 2 * cq;
            float b0 = bias[col], b1 = bias[col + 1];
            float v00 = acc[mt][nt][0] + b0, v01 = acc[mt][nt][1] + b1;
            float v10 = acc[mt][nt][2] + b0, v11 = acc[mt][nt][3] + b1;
            if (SPLIT_OUT) {
                int wc = col >> 1;
                Ch[(size_t)row * (Nn / 2) + wc]       = pack_h2(v00, v01);
                Ch[(size_t)(row + 8) * (Nn / 2) + wc] = pack_h2(v10, v11);
            } else {
                *(float2*)&C[(size_t)row * Nn + col] = make_float2(v00, v01);
                *(float2*)&C[(size_t)(row + 8) * Nn + col] = make_float2(v10, v11);
            }
        }
    }
}

// ---------------------------------------------------------------------------
// Attention (fp16 1-term flash): Q,K,P,V single fp16, fp32 accum, softmax exp
// via ex2.approx.f16x2 (produces packed P directly). Register-resident P,
// double-buffered K/V, one barrier per key-tile.
// smem u32: Q@0 (4608), 2 KV bufs of 4608 at 4608: KH@0, VH@2304.
// ---------------------------------------------------------------------------
#define QS2 36
#define KVBUF 4608
#define AKV0 4608
#define ATT_SMEM_U32 (4608 + 2 * KVBUF)

__global__ __launch_bounds__(256, 2) void attn_1t(
    const uint32_t* __restrict__ qh_g,
    const uint32_t* __restrict__ vth,
    uint32_t* __restrict__ atth)
{
    extern __shared__ uint32_t sm[];
    const uint32_t sb = smem_u32(sm);

    const int tid  = threadIdx.x;
    const int lane = tid & 31, warp = tid >> 5;
    const int g = lane >> 2, cq = lane & 3;
    const int b = blockIdx.z, h = blockIdx.y;
    const int bh = b * H + h;
    const int q0 = blockIdx.x * 128;

    const int a_r = lane & 15, a_c = (lane >> 4) * 4;

    // stage Q
#pragma unroll
    for (int i = 0; i < 4; i++) {
        int f = tid + i * 256;
        int row = f >> 3, q = (f & 7) * 4;
        size_t src = (size_t)(b * 2048 + q0 + row) * 1536 + h * 32 + q;
        CP_ASYNC16(sb + (row * QS2 + q) * 4, &qh_g[src]);
    }
    CP_COMMIT();

    auto issue_kv = [&](int kb, int buf) {
        const uint32_t kvb = AKV0 + buf * KVBUF;
#pragma unroll
        for (int i = 0; i < 2; i++) {
            int f = tid + i * 256;
            int row = f >> 3, q = (f & 7) * 4;
            size_t ksrc = (size_t)(b * 2048 + kb * 64 + row) * 1536 + 512 + h * 32 + q;
            CP_ASYNC16(sb + (kvb + row * QS2 + q) * 4, &qh_g[ksrc]);
            size_t vsrc = (size_t)(bh * 64 + row) * 1024 + kb * 32 + q;
            CP_ASYNC16(sb + (kvb + 2304 + row * QS2 + q) * 4, &vth[vsrc]);
        }
        CP_COMMIT();
    };
    issue_kv(0, 0);

    float m0v = -1e30f, m1v = -1e30f, l0s = 0.0f, l1s = 0.0f;
    float o[8][4];
#pragma unroll
    for (int nt = 0; nt < 8; nt++)
#pragma unroll
        for (int k = 0; k < 4; k++) o[nt][k] = 0.0f;

    const int rb_ = warp * 16;
    const int NKB = N / 64;

    for (int kb = 0; kb < NKB; kb++) {
        CP_WAIT(0);
        __syncthreads();
        if (kb + 1 < NKB) issue_kv(kb + 1, (kb + 1) & 1);

        const uint32_t kvb = AKV0 + (kb & 1) * KVBUF;

        // S = Q @ K^T
        float s[8][4];
#pragma unroll
        for (int nt = 0; nt < 8; nt++)
#pragma unroll
            for (int k = 0; k < 4; k++) s[nt][k] = 0.0f;

#pragma unroll
        for (int kc = 0; kc < 4; kc++) {
            uint32_t qh4[4];
            ldsm4(sb + ((rb_ + a_r) * QS2 + kc * 8 + a_c) * 4, qh4);
#pragma unroll
            for (int ntp = 0; ntp < 4; ntp++) {
                uint32_t k4[4];
                ldsm4(sb + (kvb + (ntp * 16 + a_r) * QS2 + kc * 8 + a_c) * 4, k4);
                uint32_t k0[2] = {k4[0], k4[2]};
                uint32_t k1[2] = {k4[1], k4[3]};
                mma16h(s[2 * ntp], qh4, k0);
                mma16h(s[2 * ntp + 1], qh4, k1);
            }
        }

        // online softmax (exp via ex2.f16x2 -> packed P fragments directly)
        float rm0 = -1e30f, rm1 = -1e30f;
#pragma unroll
        for (int nt = 0; nt < 8; nt++) {
            s[nt][0] *= SCALE; s[nt][1] *= SCALE; s[nt][2] *= SCALE; s[nt][3] *= SCALE;
            rm0 = fmaxf(rm0, fmaxf(s[nt][0], s[nt][1]));
            rm1 = fmaxf(rm1, fmaxf(s[nt][2], s[nt][3]));
        }
        rm0 = fmaxf(rm0, __shfl_xor_sync(0xffffffff, rm0, 1));
        rm0 = fmaxf(rm0, __shfl_xor_sync(0xffffffff, rm0, 2));
        rm1 = fmaxf(rm1, __shfl_xor_sync(0xffffffff, rm1, 1));
        rm1 = fmaxf(rm1, __shfl_xor_sync(0xffffffff, rm1, 2));

        float nm0 = fmaxf(m0v, rm0), nm1 = fmaxf(m1v, rm1);
        float a0 = __expf(m0v - nm0), a1 = __expf(m1v - nm1);
        m0v = nm0; m1v = nm1;

        uint32_t phg[8], phh[8];
#pragma unroll
        for (int nt = 0; nt < 8; nt++) {
            uint32_t t01 = pack_h2((s[nt][0] - nm0) * LOG2E, (s[nt][1] - nm0) * LOG2E);
            uint32_t t23 = pack_h2((s[nt][2] - nm1) * LOG2E, (s[nt][3] - nm1) * LOG2E);
            phg[nt] = ex2h2(t01);
            phh[nt] = ex2h2(t23);
        }
        // row sums: depth-2 HADD2 tree (partials <= 4), finish in fp32
        __half2 g01 = __hadd2(__hadd2(u2h(phg[0]), u2h(phg[1])),
                              __hadd2(u2h(phg[2]), u2h(phg[3])));
        __half2 g23 = __hadd2(__hadd2(u2h(phg[4]), u2h(phg[5])),
                              __hadd2(u2h(phg[6]), u2h(phg[7])));
        __half2 h01 = __hadd2(__hadd2(u2h(phh[0]), u2h(phh[1])),
                              __hadd2(u2h(phh[2]), u2h(phh[3])));
        __half2 h23 = __hadd2(__hadd2(u2h(phh[4]), u2h(phh[5])),
                              __hadd2(u2h(phh[6]), u2h(phh[7])));
        float2 fg0 = __half22float2(g01), fg1 = __half22float2(g23);
        float2 fh0 = __half22float2(h01), fh1 = __half22float2(h23);
        float rs0 = fg0.x + fg0.y + fg1.x + fg1.y;
        float rs1 = fh0.x + fh0.y + fh1.x + fh1.y;

        rs0 += __shfl_xor_sync(0xffffffff, rs0, 1);
        rs0 += __shfl_xor_sync(0xffffffff, rs0, 2);
        rs1 += __shfl_xor_sync(0xffffffff, rs1, 1);
        rs1 += __shfl_xor_sync(0xffffffff, rs1, 2);
        l0s = l0s * a0 + rs0;
        l1s = l1s * a1 + rs1;
#pragma unroll
        for (int nt = 0; nt < 8; nt++) {
            o[nt][0] *= a0; o[nt][1] *= a0; o[nt][2] *= a1; o[nt][3] *= a1;
        }

        // O += P @ V
#pragma unroll
        for (int kcb = 0; kcb < 4; kcb++) {
            uint32_t ah4[4] = {phg[2 * kcb], phh[2 * kcb],
                               phg[2 * kcb + 1], phh[2 * kcb + 1]};
#pragma unroll
            for (int ntp = 0; ntp < 4; ntp++) {
                uint32_t v4[4];
                ldsm4(sb + (kvb + 2304 + (ntp * 16 + a_r) * QS2 + kcb * 8 + a_c) * 4, v4);
                uint32_t v0[2] = {v4[0], v4[2]};
                uint32_t v1[2] = {v4[1], v4[3]};
                mma16h(o[2 * ntp], ah4, v0);
                mma16h(o[2 * ntp + 1], ah4, v1);
            }
        }
    }

    // normalize + write att (fp16 d-pairs)
    float inv0 = 1.0f / l0s, inv1 = 1.0f / l1s;
#pragma unroll
    for (int nt = 0; nt < 8; nt++) {
        int wc = h * 32 + nt * 4 + cq;
        size_t r0o = (size_t)(b * 2048 + q0 + rb_ + g) * 512 + wc;
        size_t r1o = (size_t)(b * 2048 + q0 + rb_ + g + 8) * 512 + wc;
        atth[r0o] = pack_h2(o[nt][0] * inv0, o[nt][1] * inv0);
        atth[r1o] = pack_h2(o[nt][2] * inv1, o[nt][3] * inv1);
    }
}

// ---------------------------------------------------------------------------
extern "C" void kernel_launch(void* const* d_in, const int* in_sizes, int n_in,
                              void* d_out, int out_size)
{
    const float* x     = (const float*)d_in[0];
    const float* Wqkv  = (const float*)d_in[1];
    const float* bqkv  = (const float*)d_in[2];
    const float* Wproj = (const float*)d_in[3];
    const float* bproj = (const float*)d_in[4];
    float* out = (float*)d_out;

    void* p;
    uint32_t *xh, *wqh, *wph, *qh, *ath, *vth;
    cudaGetSymbolAddress(&p, g_xh);     xh = (uint32_t*)p;
    cudaGetSymbolAddress(&p, g_wqkvh);  wqh = (uint32_t*)p;
    cudaGetSymbolAddress(&p, g_wprojh); wph = (uint32_t*)p;
    cudaGetSymbolAddress(&p, g_qkvh);   qh = (uint32_t*)p;
    cudaGetSymbolAddress(&p, g_atth);   ath = (uint32_t*)p;
    cudaGetSymbolAddress(&p, g_vth);    vth = (uint32_t*)p;

    cudaFuncSetAttribute(gemm_1t<true>,  cudaFuncAttributeMaxDynamicSharedMemorySize, G1SMEM_BYTES);
    cudaFuncSetAttribute(gemm_1t<false>, cudaFuncAttributeMaxDynamicSharedMemorySize, G1SMEM_BYTES);
    cudaFuncSetAttribute(attn_1t, cudaFuncAttributeMaxDynamicSharedMemorySize, ATT_SMEM_U32 * 4);

    // prep: x convert + both weight transposes in ONE launch
    prep_k<<<8192 + 1024, 256>>>(x, xh, Wqkv, Wproj, wqh, wph);

    // 1) qkv = x @ Wqkv + bqkv  (fp16 out)
    gemm_1t<true><<<dim3(3 * D / 128, BN / 128), 256, G1SMEM_BYTES>>>(
        xh, wqh, bqkv, nullptr, qh, BN, 3 * D, D);

    // 1b) build V^T (fp16)
    vtrans_k<<<dim3(N / 64, B * H), 256>>>(qh, vth);

    // 2) attention -> att (fp16 out)
    attn_1t<<<dim3(N / 128, H, B), 256, ATT_SMEM_U32 * 4>>>(qh, vth, ath);

    // 3) out = att @ Wproj + bproj  (fp32 out)
    gemm_1t<false><<<dim3(D / 128, BN / 128), 256, G1SMEM_BYTES>>>(
        ath, wph, bproj, out, nullptr, BN, D, D);
}

// round 17
// speedup vs baseline: 1.0449x; 1.0041x over previous
#include <cuda_runtime.h>
#include <cuda_bf16.h>
#include <cuda_fp16.h>
#include <math.h>
#include <stdint.h>

// Problem constants
#define B 4
#define N 2048
#define D 1024
#define H 16
#define HD 64
#define BN (B * N)            // 8192
#define SCALE 0.125f
#define LOG2E 1.44269504f

// Scratch (device globals; u32 = packed fp16x2)
__device__ uint32_t g_xh[BN * 512];        // x fp16, d-pairs
__device__ uint32_t g_wqkvh[3072 * 512];   // Wqkv^T fp16 [n][kpair]
__device__ uint32_t g_wprojh[1024 * 512];  // Wproj^T fp16 [n][kpair]
__device__ uint32_t g_qkvh[BN * 1536];     // qkv fp16, col-pairs
__device__ uint32_t g_atth[BN * 512];      // att fp16, d-pairs
__device__ uint32_t g_vth[64 * 64 * 1024]; // V^T fp16 [bh][d][keypair]

// ---------------------------------------------------------------------------
// helpers
// ---------------------------------------------------------------------------
__device__ __forceinline__ uint32_t pack_h2(float x0, float x1) {
    __half2 hh = __floats2half2_rn(x0, x1);
    return *reinterpret_cast<uint32_t*>(&hh);
}
__device__ __forceinline__ __half2 u2h(uint32_t x) {
    return *reinterpret_cast<__half2*>(&x);
}
// fp16 mma, fp32 accumulate
__device__ __forceinline__ void mma16h(float* c, const uint32_t* a, const uint32_t* b) {
    asm volatile(
        "mma.sync.aligned.m16n8k16.row.col.f32.f16.f16.f32 "
        "{%0,%1,%2,%3}, {%4,%5,%6,%7}, {%8,%9}, {%0,%1,%2,%3};"
        : "+f"(c[0]), "+f"(c[1]), "+f"(c[2]), "+f"(c[3])
        : "r"(a[0]), "r"(a[1]), "r"(a[2]), "r"(a[3]), "r"(b[0]), "r"(b[1]));
}
__device__ __forceinline__ void ldsm4(uint32_t addr, uint32_t* r) {
    asm volatile("ldmatrix.sync.aligned.m8n8.x4.shared.b16 {%0,%1,%2,%3}, [%4];"
        : "=r"(r[0]), "=r"(r[1]), "=r"(r[2]), "=r"(r[3]) : "r"(addr));
}
__device__ __forceinline__ uint32_t ex2h2(uint32_t t) {
    uint32_t r;
    asm("ex2.approx.f16x2 %0, %1;" : "=r"(r) : "r"(t));
    return r;
}
__device__ __forceinline__ uint32_t smem_u32(const void* p) {
    uint32_t a;
    asm("{ .reg .u64 t; cvta.to.shared.u64 t, %1; cvt.u32.u64 %0, t; }" : "=r"(a) : "l"(p));
    return a;
}
#define CP_ASYNC16(dst, src) \
    asm volatile("cp.async.cg.shared.global [%0], [%1], 16;" :: "r"(dst), "l"(src))
#define CP_COMMIT() asm volatile("cp.async.commit_group;" ::: "memory")
#define CP_WAIT(n)  asm volatile("cp.async.wait_group %0;" :: "n"(n) : "memory")

// ---------------------------------------------------------------------------
// prep: merged  x->fp16 (blocks [0, 8192))  +  weight transpose/convert
// ---------------------------------------------------------------------------
__global__ __launch_bounds__(256) void prep_k(
    const float* __restrict__ x, uint32_t* __restrict__ xh,
    const float* __restrict__ Wqkv, const float* __restrict__ Wproj,
    uint32_t* __restrict__ Wqkvh, uint32_t* __restrict__ Wprojh)
{
    __shared__ float sw[64 * 68];
    const int tid = threadIdx.x;
    const int bid = blockIdx.x;

    if (bid < 8192) {
        int i = bid * 256 + tid;
        float4 v = ((const float4*)x)[i];
        ((uint2*)xh)[i] = make_uint2(pack_h2(v.x, v.y), pack_h2(v.z, v.w));
        return;
    }
    const int b2 = bid - 8192;
    const int z = b2 >> 8, rem = b2 & 255;
    const float* W;
    uint32_t* Wth;
    int Nn, n0;
    if (z < 3) { W = Wqkv;  Wth = Wqkvh;  Nn = 3072; n0 = (z * 16 + (rem & 15)) * 64; }
    else       { W = Wproj; Wth = Wprojh; Nn = 1024; n0 = (rem & 15) * 64; }
    const int k0 = (rem >> 4) * 64;
#pragma unroll
    for (int i = 0; i < 4; i++) {
        int f = tid + i * 256;
        int k = f >> 4, nq = f & 15;
        float4 v = *(const float4*)&W[(size_t)(k0 + k) * Nn + n0 + nq * 4];
        *(float4*)&sw[k * 68 + nq * 4] = v;
    }
    __syncthreads();
    const int n = tid >> 2, kq = tid & 3;
    uint32_t hb[8];
#pragma unroll
    for (int j = 0; j < 8; j++) {
        int kp = kq * 8 + j;
        hb[j] = pack_h2(sw[(2 * kp) * 68 + n], sw[(2 * kp + 1) * 68 + n]);
    }
    size_t o = (size_t)(n0 + n) * 512 + k0 / 2 + kq * 8;
    *(uint4*)&Wth[o]     = make_uint4(hb[0], hb[1], hb[2], hb[3]);
    *(uint4*)&Wth[o + 4] = make_uint4(hb[4], hb[5], hb[6], hb[7]);
}

// ---------------------------------------------------------------------------
// vtrans: qkv (v section, d-pairs fp16) -> V^T fp16 [bh][d][keypair]
// ---------------------------------------------------------------------------
__global__ __launch_bounds__(256) void vtrans_k(
    const uint32_t* __restrict__ qh, uint32_t* __restrict__ vth)
{
    __shared__ uint32_t sc[32 * 66];
    const int tid = threadIdx.x;
    const int kb = blockIdx.x, bh = blockIdx.y;
    const int b = bh >> 4, h = bh & 15;
#pragma unroll
    for (int i = 0; i < 2; i++) {
        int f = tid + i * 256;
        int key = f >> 3, q = (f & 7) * 4;
        size_t src = (size_t)(b * 2048 + kb * 64 + key) * 1536 + 1024 + h * 32 + q;
        uint4 vh = *(const uint4*)&qh[src];
        sc[(q + 0) * 66 + key] = vh.x; sc[(q + 1) * 66 + key] = vh.y;
        sc[(q + 2) * 66 + key] = vh.z; sc[(q + 3) * 66 + key] = vh.w;
    }
    __syncthreads();
#pragma unroll
    for (int i = 0; i < 8; i++) {
        int f = tid + i * 256;
        int d = f >> 5, kp = f & 31;
        uint32_t sel = (d & 1) ? 0x7632u : 0x5410u;
        uint2 wh = *(const uint2*)&sc[(d >> 1) * 66 + 2 * kp];
        size_t dst = (size_t)(bh * 64 + d) * 1024 + kb * 32 + kp;
        vth[dst] = __byte_perm(wh.x, wh.y, sel);
    }
}

// ---------------------------------------------------------------------------
// GEMM fp16 1-term: C = A @ W + bias.  BK=32, double-buffered,
// single barrier per chunk. 128x128 tile, 256 thr, warps 4(m)x2(n).
// ---------------------------------------------------------------------------
#define TSTR 20
#define TILE_U32 2560
#define BUF1_U32 5120
#define G1SMEM_BYTES (2 * BUF1_U32 * 4)

template <bool SPLIT_OUT>
__global__ __launch_bounds__(256, 2) void gemm_1t(
    const uint32_t* __restrict__ Ah_g,
    const uint32_t* __restrict__ Bh_g,
    const float* __restrict__ bias,
    float* __restrict__ C, uint32_t* __restrict__ Ch,
    int M, int Nn, int K)
{
    extern __shared__ uint32_t sm[];
    const uint32_t sb = smem_u32(sm);
    const int tid = threadIdx.x;
    const int lane = tid & 31, warp = tid >> 5;
    const int g = lane >> 2, cq = lane & 3;
    const int wm = (warp >> 1) * 32, wn = (warp & 1) * 64;
    const int m0 = blockIdx.y * 128, n0 = blockIdx.x * 128;
    const int kwtot = K / 2;

    const int a_r = lane & 15, a_c = (lane >> 4) * 4;

    float acc[2][8][4];
#pragma unroll
    for (int mt = 0; mt < 2; mt++)
#pragma unroll
        for (int nt = 0; nt < 8; nt++)
#pragma unroll
            for (int k = 0; k < 4; k++) acc[mt][nt][k] = 0.0f;

    auto issue = [&](int c, int buf) {
        const int kw = c * 16;
        const uint32_t bb = sb + buf * (BUF1_U32 * 4);
#pragma unroll
        for (int i = 0; i < 2; i++) {
            int f = tid + i * 256;
            int r = f >> 2, q = (f & 3) * 4;
            uint32_t d0 = bb + (r * TSTR + q) * 4;
            CP_ASYNC16(d0,                &Ah_g[(size_t)(m0 + r) * kwtot + kw + q]);
            CP_ASYNC16(d0 + TILE_U32 * 4, &Bh_g[(size_t)(n0 + r) * kwtot + kw + q]);
        }
        CP_COMMIT();
    };

    const int nch = K / 32;
    issue(0, 0);
    for (int c = 0; c < nch; c++) {
        CP_WAIT(0);
        __syncthreads();
        if (c + 1 < nch) issue(c + 1, (c + 1) & 1);

        const uint32_t bufb = sb + (c & 1) * (BUF1_U32 * 4);
#pragma unroll
        for (int kc = 0; kc < 2; kc++) {
            uint32_t ah[2][4];
#pragma unroll
            for (int mt = 0; mt < 2; mt++)
                ldsm4(bufb + ((wm + mt * 16 + a_r) * TSTR + kc * 8 + a_c) * 4, ah[mt]);
#pragma unroll
            for (int ntp = 0; ntp < 4; ntp++) {
                uint32_t b4[4];
                ldsm4(bufb + TILE_U32 * 4 +
                      ((wn + ntp * 16 + a_r) * TSTR + kc * 8 + a_c) * 4, b4);
                uint32_t b0[2] = {b4[0], b4[2]};
                uint32_t b1[2] = {b4[1], b4[3]};
#pragma unroll
                for (int mt = 0; mt < 2; mt++) mma16h(acc[mt][2 * ntp], ah[mt], b0);
#pragma unroll
                for (int mt = 0; mt < 2; mt++) mma16h(acc[mt][2 * ntp + 1], ah[mt], b1);
            }
        }
    }

#pragma unroll
    for (int mt = 0; mt < 2; mt++) {
#pragma unroll
        for (int nt = 0; nt < 8; nt++) {
            int row = m0 + wm + mt * 16 + g;
            int col = n0 + wn + nt * 8 + 2 * cq;
            float b0 = bias[col], b1 = bias[col + 1];
            float v00 = acc[mt][nt][0] + b0, v01 = acc[mt][nt][1] + b1;
            float v10 = acc[mt][nt][2] + b0, v11 = acc[mt][nt][3] + b1;
            if (SPLIT_OUT) {
                int wc = col >> 1;
                Ch[(size_t)row * (Nn / 2) + wc]       = pack_h2(v00, v01);
                Ch[(size_t)(row + 8) * (Nn / 2) + wc] = pack_h2(v10, v11);
            } else {
                *(float2*)&C[(size_t)row * Nn + col] = make_float2(v00, v01);
                *(float2*)&C[(size_t)(row + 8) * Nn + col] = make_float2(v10, v11);
            }
        }
    }
}

// ---------------------------------------------------------------------------
// Attention (fp16 flash, ONLINE-max softmax via ex2.f16x2): Q,K,P,V single
// fp16, fp32 accum. Q fragments hoisted out of the key loop. Register P,
// double-buffered K/V, one barrier per key-tile.
// smem u32: Q@0 (4608), 2 KV bufs of 4608 at 4608: KH@0, VH@2304.
// ---------------------------------------------------------------------------
#define QS2 36
#define KVBUF 4608
#define AKV0 4608
#define ATT_SMEM_U32 (4608 + 2 * KVBUF)

__global__ __launch_bounds__(256, 2) void attn_1t(
    const uint32_t* __restrict__ qh_g,
    const uint32_t* __restrict__ vth,
    uint32_t* __restrict__ atth)
{
    extern __shared__ uint32_t sm[];
    const uint32_t sb = smem_u32(sm);

    const int tid  = threadIdx.x;
    const int lane = tid & 31, warp = tid >> 5;
    const int g = lane >> 2, cq = lane & 3;
    const int b = blockIdx.z, h = blockIdx.y;
    const int bh = b * H + h;
    const int q0 = blockIdx.x * 128;
    const int rb_ = warp * 16;

    const int a_r = lane & 15, a_c = (lane >> 4) * 4;

    // stage Q (group 0)
#pragma unroll
    for (int i = 0; i < 4; i++) {
        int f = tid + i * 256;
        int row = f >> 3, q = (f & 7) * 4;
        size_t src = (size_t)(b * 2048 + q0 + row) * 1536 + h * 32 + q;
        CP_ASYNC16(sb + (row * QS2 + q) * 4, &qh_g[src]);
    }
    CP_COMMIT();

    auto issue_kv = [&](int kb, int buf) {
        const uint32_t kvb = AKV0 + buf * KVBUF;
#pragma unroll
        for (int i = 0; i < 2; i++) {
            int f = tid + i * 256;
            int row = f >> 3, q = (f & 7) * 4;
            size_t ksrc = (size_t)(b * 2048 + kb * 64 + row) * 1536 + 512 + h * 32 + q;
            CP_ASYNC16(sb + (kvb + row * QS2 + q) * 4, &qh_g[ksrc]);
            size_t vsrc = (size_t)(bh * 64 + row) * 1024 + kb * 32 + q;
            CP_ASYNC16(sb + (kvb + 2304 + row * QS2 + q) * 4, &vth[vsrc]);
        }
        CP_COMMIT();
    };
    issue_kv(0, 0);   // group 1

    // Q fragments: hoisted, loop-invariant
    CP_WAIT(1);       // Q (group 0) complete; kv group may still be in flight
    __syncthreads();
    uint32_t qf[4][4];
#pragma unroll
    for (int kc = 0; kc < 4; kc++)
        ldsm4(sb + ((rb_ + a_r) * QS2 + kc * 8 + a_c) * 4, qf[kc]);

    float m0v = -1e30f, m1v = -1e30f, l0s = 0.0f, l1s = 0.0f;
    float o[8][4];
#pragma unroll
    for (int nt = 0; nt < 8; nt++)
#pragma unroll
        for (int k = 0; k < 4; k++) o[nt][k] = 0.0f;

    const int NKB = N / 64;

    for (int kb = 0; kb < NKB; kb++) {
        CP_WAIT(0);
        __syncthreads();
        if (kb + 1 < NKB) issue_kv(kb + 1, (kb + 1) & 1);

        const uint32_t kvb = AKV0 + (kb & 1) * KVBUF;

        // S = Q @ K^T
        float s[8][4];
#pragma unroll
        for (int nt = 0; nt < 8; nt++)
#pragma unroll
            for (int k = 0; k < 4; k++) s[nt][k] = 0.0f;

#pragma unroll
        for (int kc = 0; kc < 4; kc++) {
#pragma unroll
            for (int ntp = 0; ntp < 4; ntp++) {
                uint32_t k4[4];
                ldsm4(sb + (kvb + (ntp * 16 + a_r) * QS2 + kc * 8 + a_c) * 4, k4);
                uint32_t k0[2] = {k4[0], k4[2]};
                uint32_t k1[2] = {k4[1], k4[3]};
                mma16h(s[2 * ntp], qf[kc], k0);
                mma16h(s[2 * ntp + 1], qf[kc], k1);
            }
        }

        // online softmax (exp via ex2.f16x2 -> packed P fragments directly)
        float rm0 = -1e30f, rm1 = -1e30f;
#pragma unroll
        for (int nt = 0; nt < 8; nt++) {
            s[nt][0] *= SCALE; s[nt][1] *= SCALE; s[nt][2] *= SCALE; s[nt][3] *= SCALE;
            rm0 = fmaxf(rm0, fmaxf(s[nt][0], s[nt][1]));
            rm1 = fmaxf(rm1, fmaxf(s[nt][2], s[nt][3]));
        }
        rm0 = fmaxf(rm0, __shfl_xor_sync(0xffffffff, rm0, 1));
        rm0 = fmaxf(rm0, __shfl_xor_sync(0xffffffff, rm0, 2));
        rm1 = fmaxf(rm1, __shfl_xor_sync(0xffffffff, rm1, 1));
        rm1 = fmaxf(rm1, __shfl_xor_sync(0xffffffff, rm1, 2));

        float nm0 = fmaxf(m0v, rm0), nm1 = fmaxf(m1v, rm1);
        float a0 = __expf(m0v - nm0), a1 = __expf(m1v - nm1);
        m0v = nm0; m1v = nm1;

        uint32_t phg[8], phh[8];
#pragma unroll
        for (int nt = 0; nt < 8; nt++) {
            uint32_t t01 = pack_h2((s[nt][0] - nm0) * LOG2E, (s[nt][1] - nm0) * LOG2E);
            uint32_t t23 = pack_h2((s[nt][2] - nm1) * LOG2E, (s[nt][3] - nm1) * LOG2E);
            phg[nt] = ex2h2(t01);
            phh[nt] = ex2h2(t23);
        }
        // row sums: depth-2 HADD2 tree, finish fp32
        __half2 g01 = __hadd2(__hadd2(u2h(phg[0]), u2h(phg[1])),
                              __hadd2(u2h(phg[2]), u2h(phg[3])));
        __half2 g23 = __hadd2(__hadd2(u2h(phg[4]), u2h(phg[5])),
                              __hadd2(u2h(phg[6]), u2h(phg[7])));
        __half2 h01 = __hadd2(__hadd2(u2h(phh[0]), u2h(phh[1])),
                              __hadd2(u2h(phh[2]), u2h(phh[3])));
        __half2 h23 = __hadd2(__hadd2(u2h(phh[4]), u2h(phh[5])),
                              __hadd2(u2h(phh[6]), u2h(phh[7])));
        float2 fg0 = __half22float2(g01), fg1 = __half22float2(g23);
        float2 fh0 = __half22float2(h01), fh1 = __half22float2(h23);
        float rs0 = fg0.x + fg0.y + fg1.x + fg1.y;
        float rs1 = fh0.x + fh0.y + fh1.x + fh1.y;
        rs0 += __shfl_xor_sync(0xffffffff, rs0, 1);
        rs0 += __shfl_xor_sync(0xffffffff, rs0, 2);
        rs1 += __shfl_xor_sync(0xffffffff, rs1, 1);
        rs1 += __shfl_xor_sync(0xffffffff, rs1, 2);
        l0s = l0s * a0 + rs0;
        l1s = l1s * a1 + rs1;
#pragma unroll
        for (int nt = 0; nt < 8; nt++) {
            o[nt][0] *= a0; o[nt][1] *= a0; o[nt][2] *= a1; o[nt][3] *= a1;
        }

        // O += P @ V
#pragma unroll
        for (int kcb = 0; kcb < 4; kcb++) {
            uint32_t ah4[4] = {phg[2 * kcb], phh[2 * kcb],
                               phg[2 * kcb + 1], phh[2 * kcb + 1]};
#pragma unroll
            for (int ntp = 0; ntp < 4; ntp++) {
                uint32_t v4[4];
                ldsm4(sb + (kvb + 2304 + (ntp * 16 + a_r) * QS2 + kcb * 8 + a_c) * 4, v4);
                uint32_t v0[2] = {v4[0], v4[2]};
                uint32_t v1[2] = {v4[1], v4[3]};
                mma16h(o[2 * ntp], ah4, v0);
                mma16h(o[2 * ntp + 1], ah4, v1);
            }
        }
    }

    // normalize + write att (fp16 d-pairs)
    float inv0 = 1.0f / l0s, inv1 = 1.0f / l1s;
#pragma unroll
    for (int nt = 0; nt < 8; nt++) {
        int wc = h * 32 + nt * 4 + cq;
        size_t r0o = (size_t)(b * 2048 + q0 + rb_ + g) * 512 + wc;
        size_t r1o = (size_t)(b * 2048 + q0 + rb_ + g + 8) * 512 + wc;
        atth[r0o] = pack_h2(o[nt][0] * inv0, o[nt][1] * inv0);
        atth[r1o] = pack_h2(o[nt][2] * inv1, o[nt][3] * inv1);
    }
}

// ---------------------------------------------------------------------------
extern "C" void kernel_launch(void* const* d_in, const int* in_sizes, int n_in,
                              void* d_out, int out_size)
{
    const float* x     = (const float*)d_in[0];
    const float* Wqkv  = (const float*)d_in[1];
    const float* bqkv  = (const float*)d_in[2];
    const float* Wproj = (const float*)d_in[3];
    const float* bproj = (const float*)d_in[4];
    float* out = (float*)d_out;

    void* p;
    uint32_t *xh, *wqh, *wph, *qh, *ath, *vth;
    cudaGetSymbolAddress(&p, g_xh);     xh = (uint32_t*)p;
    cudaGetSymbolAddress(&p, g_wqkvh);  wqh = (uint32_t*)p;
    cudaGetSymbolAddress(&p, g_wprojh); wph = (uint32_t*)p;
    cudaGetSymbolAddress(&p, g_qkvh);   qh = (uint32_t*)p;
    cudaGetSymbolAddress(&p, g_atth);   ath = (uint32_t*)p;
    cudaGetSymbolAddress(&p, g_vth);    vth = (uint32_t*)p;

    cudaFuncSetAttribute(gemm_1t<true>,  cudaFuncAttributeMaxDynamicSharedMemorySize, G1SMEM_BYTES);
    cudaFuncSetAttribute(gemm_1t<false>, cudaFuncAttributeMaxDynamicSharedMemorySize, G1SMEM_BYTES);
    cudaFuncSetAttribute(attn_1t, cudaFuncAttributeMaxDynamicSharedMemorySize, ATT_SMEM_U32 * 4);

    // prep: x convert + both weight transposes in ONE launch
    prep_k<<<8192 + 1024, 256>>>(x, xh, Wqkv, Wproj, wqh, wph);

    // 1) qkv = x @ Wqkv + bqkv  (fp16 out)
    gemm_1t<true><<<dim3(3 * D / 128, BN / 128), 256, G1SMEM_BYTES>>>(
        xh, wqh, bqkv, nullptr, qh, BN, 3 * D, D);

    // 1b) build V^T (fp16)
    vtrans_k<<<dim3(N / 64, B * H), 256>>>(qh, vth);

    // 2) attention -> att (fp16 out)
    attn_1t<<<dim3(N / 128, H, B), 256, ATT_SMEM_U32 * 4>>>(qh, vth, ath);

    // 3) out = att @ Wproj + bproj  (fp32 out)
    gemm_1t<false><<<dim3(D / 128, BN / 128), 256, G1SMEM_BYTES>>>(
        ath, wph, bproj, out, nullptr, BN, D, D);
}